// round 16
// baseline (speedup 1.0000x reference)
#include <cuda_runtime.h>
#include <cuda_fp16.h>
#include <stdint.h>

#define NN   50000
#define NE   800000
#define FIN  128
#define DIM  256
#define NG   512
#define NL   3
#define OUTD (NL*DIM)   // 768
#define BN_EPS 1e-5f

// Scratch — two f32 feature buffers (ping-pong across layers; the fused
// kernel reads prev-layer features of ARBITRARY nodes while writing its own
// rows, so read and write targets must be distinct).
__device__ float4 g_bufB4[NN*DIM/4];
__device__ float4 g_bufC4[NN*DIM/4];
__device__ float  g_stats[NL][2*DIM];     // per-layer column sum, sumsq
__device__ float  g_sc[DIM], g_sh[DIM];   // published BN affine of prev layer
__device__ int    g_idx64;
// fp16 weight images, N-major ([n][k]) per (t,chunk) 128x32 tile.
__device__ __half g_whi[360448];
// CSR scratch
__device__ int g_deg[NN];
__device__ int g_rowstart[NN + 1];
__device__ int g_pos[NE];
__device__ int g_src32[NE];
__device__ int g_dst32[NE];
__device__ int g_eidx[NE];

// ---------------------------------------------------------------------------
__device__ __forceinline__ uint32_t smem_u32(const void* p) {
    uint32_t a;
    asm("{ .reg .u64 t; cvta.to.shared.u64 t, %1; cvt.u32.u64 %0, t; }" : "=r"(a) : "l"(p));
    return a;
}
__device__ __forceinline__ uint32_t pack_hf2(float a, float b) {
    uint32_t r;
    asm("cvt.rn.f16x2.f32 %0, %1, %2;" : "=r"(r) : "f"(b), "f"(a));
    return r;
}
__device__ __forceinline__ void splithf(float x, float& h, float& l) {
    __half hb = __float2half_rn(x);
    h = __half2float(hb);
    l = x - h;
}
#define LDSM_X4(r0, r1, r2, r3, addr)                                          \
    asm volatile("ldmatrix.sync.aligned.m8n8.x4.shared.b16 {%0,%1,%2,%3}, [%4];" \
                 : "=r"(r0), "=r"(r1), "=r"(r2), "=r"(r3) : "r"(addr))
#define MMA_F16(c, a0, a1, a2, a3, b0, b1)                                     \
    asm volatile(                                                              \
        "mma.sync.aligned.m16n8k16.row.col.f32.f16.f16.f32 "                   \
        "{%0,%1,%2,%3}, {%4,%5,%6,%7}, {%8,%9}, {%0,%1,%2,%3};"                \
        : "+f"(c[0]), "+f"(c[1]), "+f"(c[2]), "+f"(c[3])                       \
        : "r"(a0), "r"(a1), "r"(a2), "r"(a3), "r"(b0), "r"(b1))
#define CP_ASYNC16(dst, src)                                                   \
    asm volatile("cp.async.ca.shared.global [%0], [%1], 16;"                   \
                 :: "r"(dst), "l"(src) : "memory")
#define CP_COMMIT() asm volatile("cp.async.commit_group;" ::: "memory")

__device__ __forceinline__ long long load_idx(const void* p, long long i, int is64) {
    return is64 ? ((const long long*)p)[i] : (long long)((const int*)p)[i];
}

// ---------------------------------------------------------------------------
// prep: dtype detect, edge decode + degree histogram, fp16 weight images,
// pooled + stats zeroing. (g_deg re-zeroed by scan.)
#define WTOT 360448
__global__ void prep_kernel(const void* __restrict__ ei,
                            const float* w0, const float* w1, const float* w2,
                            const float* w3, const float* w4, const float* w5,
                            __half* __restrict__ whi,
                            float* __restrict__ pooled) {
    int stride = gridDim.x * blockDim.x;
    int gidx = blockIdx.x * blockDim.x + threadIdx.x;
    unsigned int z = 0u;
    const unsigned int* er = (const unsigned int*)ei;
#pragma unroll
    for (int k = 0; k < 8; k++) z |= er[2 * k + 1];
    int is64 = (z == 0u) ? 1 : 0;
    if (gidx == 0) g_idx64 = is64;

    if (gidx < NG * OUTD) pooled[gidx] = 0.f;
    if (gidx < NL * 2 * DIM) ((float*)g_stats)[gidx] = 0.f;

    for (int e = gidx; e < NE; e += stride) {
        int s = (int)load_idx(ei, e, is64);
        int d = (int)load_idx(ei, (long long)NE + e, is64);
        g_src32[e] = s;
        g_dst32[e] = d;
        g_pos[e] = atomicAdd(&g_deg[d], 1);
    }
    const float* ws[6] = {w0, w1, w2, w3, w4, w5};
    const int woffs[6] = {0, 32768, 98304, 163840, 229376, 294912};
    for (int idx = gidx; idx < WTOT; idx += stride) {
        int wsel, local, K;
        if (idx < 32768) { wsel = 0; local = idx; K = FIN; }
        else { wsel = 1 + ((idx - 32768) >> 16); local = (idx - 32768) & 65535; K = DIM; }
        int k = local >> 8, n = local & 255;
        int nch = K >> 5;
        int t = n >> 7, nl = n & 127, c = k >> 5, kk = k & 31;
        int off = woffs[wsel] + (t * nch + c) * 4096 + nl * 32 + kk;
        whi[off] = __float2half_rn(ws[wsel][local]);
    }
}

// Single-block scan: degrees -> rowstart (+ sentinel), then re-zero degrees.
__global__ void scan_kernel() {
    __shared__ int sm[1024];
    int t = threadIdx.x;
    const int CH = (NN + 1023) / 1024;
    int b0 = t * CH, b1 = min(b0 + CH, NN);
    int s = 0;
    for (int i = b0; i < b1; i++) s += g_deg[i];
    sm[t] = s;
    __syncthreads();
    for (int off = 1; off < 1024; off <<= 1) {
        int v = (t >= off) ? sm[t - off] : 0;
        __syncthreads();
        sm[t] += v;
        __syncthreads();
    }
    int run = (t == 0) ? 0 : sm[t - 1];
    for (int i = b0; i < b1; i++) { g_rowstart[i] = run; run += g_deg[i]; }
    if (t == 1023) g_rowstart[NN] = sm[1023];
    for (int i = b0; i < b1; i++) g_deg[i] = 0;
}

__global__ void fillcsr_kernel() {
    int stride = gridDim.x * blockDim.x;
    for (int e = blockIdx.x * blockDim.x + threadIdx.x; e < NE; e += stride)
        g_eidx[g_rowstart[g_dst32[e]] + g_pos[e]] = g_src32[e];
}

// ---------------------------------------------------------------------------
// Fully fused layer: gather(+BN affine) -> GEMM1 -> GEMM2 -> m + BN stats.
// 512 threads, 128-row tile, full N=256. agg and t never touch gmem.
// h (read) and Cf (write) MUST be different buffers (cross-CTA gather reads).
// SMEM map:
//   B stage0 [0, 20480), B stage1 [20480, 40960)
//   A/t hi   [40960, 108544)   stride 528 (conflict-free for ldmatrix)
//   A/t lo   [108544, 176128)
#define BSTG   20480
#define A_HI   40960
#define A_LO   108544
#define TSTR   528
#define ARS    80
#define MLP_SMEM 176128

__global__ void __launch_bounds__(512) layer_fused(
    const float* __restrict__ h, int K1, int use_affine,
    const __half* __restrict__ W1h, const float* __restrict__ b1,
    const __half* __restrict__ W2h, const float* __restrict__ b2,
    float* __restrict__ Cf, float* __restrict__ stats, int M) {
    extern __shared__ __align__(16) char dsm[];
    int tid = threadIdx.x, wid = tid >> 5, lane = tid & 31;
    int bm = blockIdx.x;
    int nch1 = K1 >> 5;

    uint32_t sb = smem_u32(dsm);
    int m_off = (wid & 3) * 32;
    int n_off = (wid >> 2) * 64;

    int aRowL = (lane & 7) + ((lane >> 3) & 1) * 8;
    int aColL = (lane >> 4) * 16;
    int bRowL = ((lane >> 4) * 8) + (lane & 7);
    int bColL = ((lane >> 3) & 1) * 16;
    int gid = lane >> 2, tig = lane & 3;

    auto issueB = [&](const __half* W, int nch, int c, uint32_t stg) {
#pragma unroll
        for (int i = 0; i < 2; i++) {
            int p = tid + i * 512;
            int row = p >> 2, seg = p & 3;
            int t = row >> 7, nl = row & 127;
            long long srcIdx = ((long long)(t * nch + c) * 512) + nl * 4 + seg;
            CP_ASYNC16(stg + row * ARS + seg * 16, (const uint4*)W + srcIdx);
        }
    };

    // B1 chunk 0 in flight while we gather
    issueB(W1h, nch1, 0, sb);
    CP_COMMIT();

    // ===== gather phase: each warp gathers 8 nodes into SMEM A (hi/lo) =====
    {
        int F4 = K1 >> 2;
        bool wide = (F4 == 64);
        const float4* hv = (const float4*)h;
        for (int i = 0; i < 8; i++) {
            int row = wid * 8 + i;
            int node = bm * 128 + row;
            float4 a0 = make_float4(0.f, 0.f, 0.f, 0.f);
            float4 a1 = a0;
            if (node < NN) {
                int start = g_rowstart[node];
                int deg = g_rowstart[node + 1] - start;
                const float4* hp = hv + (long long)node * F4 + lane;
                a0 = hp[0];
                if (wide) a1 = hp[32];
                for (int i0 = 0; i0 < deg; i0 += 32) {
                    int mye = (i0 + lane < deg) ? g_eidx[start + i0 + lane] : 0;
                    int cnt = min(32, deg - i0);
                    for (int j = 0; j < cnt; j++) {
                        int s = __shfl_sync(0xffffffffu, mye, j);
                        const float4* sp = hv + (long long)s * F4 + lane;
                        float4 v = sp[0];
                        a0.x += v.x; a0.y += v.y; a0.z += v.z; a0.w += v.w;
                        if (wide) {
                            float4 u = sp[32];
                            a1.x += u.x; a1.y += u.y; a1.z += u.z; a1.w += u.w;
                        }
                    }
                }
                if (use_affine) {
                    int c0 = lane * 4;
                    float cnt = (float)(deg + 1);
                    a0.x = g_sc[c0+0]*a0.x + cnt*g_sh[c0+0];
                    a0.y = g_sc[c0+1]*a0.y + cnt*g_sh[c0+1];
                    a0.z = g_sc[c0+2]*a0.z + cnt*g_sh[c0+2];
                    a0.w = g_sc[c0+3]*a0.w + cnt*g_sh[c0+3];
                    if (wide) {
                        int c1 = 128 + c0;
                        a1.x = g_sc[c1+0]*a1.x + cnt*g_sh[c1+0];
                        a1.y = g_sc[c1+1]*a1.y + cnt*g_sh[c1+1];
                        a1.z = g_sc[c1+2]*a1.z + cnt*g_sh[c1+2];
                        a1.w = g_sc[c1+3]*a1.w + cnt*g_sh[c1+3];
                    }
                }
            }
            // split + store into SMEM A region (stride TSTR)
            uint32_t ad = sb + A_HI + row * TSTR + lane * 8;
            {
                float h0,l0,h1,l1,h2,l2,h3,l3;
                splithf(a0.x,h0,l0); splithf(a0.y,h1,l1);
                splithf(a0.z,h2,l2); splithf(a0.w,h3,l3);
                asm volatile("st.shared.v2.b32 [%0], {%1,%2};"
                             :: "r"(ad), "r"(pack_hf2(h0,h1)), "r"(pack_hf2(h2,h3)) : "memory");
                asm volatile("st.shared.v2.b32 [%0], {%1,%2};"
                             :: "r"(ad + (A_LO - A_HI)), "r"(pack_hf2(l0,l1)), "r"(pack_hf2(l2,l3)) : "memory");
            }
            if (wide) {
                float h0,l0,h1,l1,h2,l2,h3,l3;
                splithf(a1.x,h0,l0); splithf(a1.y,h1,l1);
                splithf(a1.z,h2,l2); splithf(a1.w,h3,l3);
                asm volatile("st.shared.v2.b32 [%0], {%1,%2};"
                             :: "r"(ad + 256), "r"(pack_hf2(h0,h1)), "r"(pack_hf2(h2,h3)) : "memory");
                asm volatile("st.shared.v2.b32 [%0], {%1,%2};"
                             :: "r"(ad + 256 + (A_LO - A_HI)), "r"(pack_hf2(l0,l1)), "r"(pack_hf2(l2,l3)) : "memory");
            }
        }
    }
    __syncthreads();

    float acc[2][8][4] = {};

    // ===== phase 1: t = relu(A @ W1 + b1); A read in place from SMEM =====
    for (int c = 0; c < nch1; c++) {
        uint32_t stg = sb + (c & 1) * BSTG;
        if (c + 1 < nch1) {
            issueB(W1h, nch1, c + 1, sb + ((c + 1) & 1) * BSTG);
            CP_COMMIT();
            asm volatile("cp.async.wait_group 1;" ::: "memory");
        } else {
            asm volatile("cp.async.wait_group 0;" ::: "memory");
        }
        __syncthreads();
#pragma unroll
        for (int ks = 0; ks < 2; ks++) {
            uint32_t aH[2][4], aL[2][4];
#pragma unroll
            for (int mt = 0; mt < 2; mt++) {
                uint32_t ad = sb + A_HI + (m_off + mt * 16 + aRowL) * TSTR + c * 64 + ks * 32 + aColL;
                LDSM_X4(aH[mt][0], aH[mt][1], aH[mt][2], aH[mt][3], ad);
                LDSM_X4(aL[mt][0], aL[mt][1], aL[mt][2], aL[mt][3], ad + (A_LO - A_HI));
            }
#pragma unroll
            for (int p = 0; p < 4; p++) {
                uint32_t bH[2][2];
                uint32_t ad = stg + (n_off + p * 16 + bRowL) * ARS + ks * 32 + bColL;
                LDSM_X4(bH[0][0], bH[0][1], bH[1][0], bH[1][1], ad);
#pragma unroll
                for (int mt = 0; mt < 2; mt++)
#pragma unroll
                    for (int q = 0; q < 2; q++)
                        MMA_F16(acc[mt][2*p+q], aH[mt][0], aH[mt][1], aH[mt][2], aH[mt][3],
                                bH[q][0], bH[q][1]);
#pragma unroll
                for (int mt = 0; mt < 2; mt++)
#pragma unroll
                    for (int q = 0; q < 2; q++)
                        MMA_F16(acc[mt][2*p+q], aL[mt][0], aL[mt][1], aL[mt][2], aL[mt][3],
                                bH[q][0], bH[q][1]);
            }
        }
        __syncthreads();
    }

    // ===== phase-1 epilogue: bias+relu+split -> t OVERWRITES A region =====
#pragma unroll
    for (int nt = 0; nt < 8; nt++) {
        int col = n_off + nt * 8 + tig * 2;
        float c0 = b1[col], c1 = b1[col + 1];
#pragma unroll
        for (int mt = 0; mt < 2; mt++) {
            float* cc = acc[mt][nt];
            int r0 = m_off + mt * 16 + gid;
            {
                float o0 = fmaxf(cc[0] + c0, 0.f);
                float o1 = fmaxf(cc[1] + c1, 0.f);
                float h0,l0,h1,l1;
                splithf(o0,h0,l0); splithf(o1,h1,l1);
                uint32_t ad = sb + A_HI + r0 * TSTR + col * 2;
                asm volatile("st.shared.b32 [%0], %1;" :: "r"(ad), "r"(pack_hf2(h0,h1)) : "memory");
                asm volatile("st.shared.b32 [%0], %1;" :: "r"(ad + (A_LO - A_HI)), "r"(pack_hf2(l0,l1)) : "memory");
            }
            {
                float o2 = fmaxf(cc[2] + c0, 0.f);
                float o3 = fmaxf(cc[3] + c1, 0.f);
                float h2,l2,h3,l3;
                splithf(o2,h2,l2); splithf(o3,h3,l3);
                uint32_t ad = sb + A_HI + (r0 + 8) * TSTR + col * 2;
                asm volatile("st.shared.b32 [%0], %1;" :: "r"(ad), "r"(pack_hf2(h2,h3)) : "memory");
                asm volatile("st.shared.b32 [%0], %1;" :: "r"(ad + (A_LO - A_HI)), "r"(pack_hf2(l2,l3)) : "memory");
            }
            cc[0] = cc[1] = cc[2] = cc[3] = 0.f;
        }
    }
    __syncthreads();

    // ===== phase 2: m = relu(t @ W2 + b2) =====
    issueB(W2h, 8, 0, sb);
    CP_COMMIT();
    for (int c = 0; c < 8; c++) {
        uint32_t stg = sb + (c & 1) * BSTG;
        if (c + 1 < 8) {
            issueB(W2h, 8, c + 1, sb + ((c + 1) & 1) * BSTG);
            CP_COMMIT();
            asm volatile("cp.async.wait_group 1;" ::: "memory");
        } else {
            asm volatile("cp.async.wait_group 0;" ::: "memory");
        }
        __syncthreads();
#pragma unroll
        for (int ks = 0; ks < 2; ks++) {
            uint32_t aH[2][4], aL[2][4];
#pragma unroll
            for (int mt = 0; mt < 2; mt++) {
                uint32_t ad = sb + A_HI + (m_off + mt * 16 + aRowL) * TSTR + c * 64 + ks * 32 + aColL;
                LDSM_X4(aH[mt][0], aH[mt][1], aH[mt][2], aH[mt][3], ad);
                LDSM_X4(aL[mt][0], aL[mt][1], aL[mt][2], aL[mt][3], ad + (A_LO - A_HI));
            }
#pragma unroll
            for (int p = 0; p < 4; p++) {
                uint32_t bH[2][2];
                uint32_t ad = stg + (n_off + p * 16 + bRowL) * ARS + ks * 32 + bColL;
                LDSM_X4(bH[0][0], bH[0][1], bH[1][0], bH[1][1], ad);
#pragma unroll
                for (int mt = 0; mt < 2; mt++)
#pragma unroll
                    for (int q = 0; q < 2; q++)
                        MMA_F16(acc[mt][2*p+q], aH[mt][0], aH[mt][1], aH[mt][2], aH[mt][3],
                                bH[q][0], bH[q][1]);
#pragma unroll
                for (int mt = 0; mt < 2; mt++)
#pragma unroll
                    for (int q = 0; q < 2; q++)
                        MMA_F16(acc[mt][2*p+q], aL[mt][0], aL[mt][1], aL[mt][2], aL[mt][3],
                                bH[q][0], bH[q][1]);
            }
        }
        __syncthreads();
    }

    // ===== final epilogue: bias + relu, f32 out + fused BN stats =====
#pragma unroll
    for (int nt = 0; nt < 8; nt++) {
        int col = n_off + nt * 8 + tig * 2;
        float c0 = b2[col], c1 = b2[col + 1];
        float s0 = 0.f, s1 = 0.f, q0 = 0.f, q1 = 0.f;
#pragma unroll
        for (int mt = 0; mt < 2; mt++) {
            int r0 = bm * 128 + m_off + mt * 16 + gid;
            float* cc = acc[mt][nt];
            if (r0 < M) {
                float o0 = fmaxf(cc[0] + c0, 0.f);
                float o1 = fmaxf(cc[1] + c1, 0.f);
                float2 o; o.x = o0; o.y = o1;
                *(float2*)(Cf + (long long)r0 * 256 + col) = o;
                s0 += o0; s1 += o1; q0 += o0 * o0; q1 += o1 * o1;
            }
            if (r0 + 8 < M) {
                float o2 = fmaxf(cc[2] + c0, 0.f);
                float o3 = fmaxf(cc[3] + c1, 0.f);
                float2 o; o.x = o2; o.y = o3;
                *(float2*)(Cf + (long long)(r0 + 8) * 256 + col) = o;
                s0 += o2; s1 += o3; q0 += o2 * o2; q1 += o3 * o3;
            }
        }
#pragma unroll
        for (int m = 4; m < 32; m <<= 1) {
            s0 += __shfl_xor_sync(0xffffffffu, s0, m);
            s1 += __shfl_xor_sync(0xffffffffu, s1, m);
            q0 += __shfl_xor_sync(0xffffffffu, q0, m);
            q1 += __shfl_xor_sync(0xffffffffu, q1, m);
        }
        if (gid == 0) {
            atomicAdd(&stats[col], s0);
            atomicAdd(&stats[col + 1], s1);
            atomicAdd(&stats[DIM + col], q0);
            atomicAdd(&stats[DIM + col + 1], q1);
        }
    }
}

// ---------------------------------------------------------------------------
// Per-layer output: norm(m) -> outn slice + pooled sums. Block 0 publishes
// the affine for the next layer's fused gather.
#define ROWS_PB 128
__global__ void outpool_kernel(const float* __restrict__ m,
                               const float* __restrict__ g, const float* __restrict__ b,
                               const void* __restrict__ batch,
                               float* __restrict__ outn,
                               float* __restrict__ pooled,
                               const float* __restrict__ stats, int layer) {
    int col = threadIdx.x;
    int is64 = g_idx64;
    float mu  = stats[col] * (1.f / NN);
    float var = stats[DIM + col] * (1.f / NN) - mu * mu;
    float sc  = g[col] * rsqrtf(var + BN_EPS);
    float sh  = b[col] - mu * sc;
    if (blockIdx.x == 0) { g_sc[col] = sc; g_sh[col] = sh; }

    int n0 = blockIdx.x * ROWS_PB;
    int n1 = min(n0 + ROWS_PB, NN);
    float acc = 0.f;
    long long cur = load_idx(batch, n0, is64);
    for (int n = n0; n < n1; n++) {
        float v = m[(long long)n * DIM + col] * sc + sh;
        outn[(long long)n * OUTD + layer * DIM + col] = v;
        long long bb = load_idx(batch, n, is64);
        if (bb != cur) {
            atomicAdd(&pooled[cur * OUTD + layer * DIM + col], acc);
            acc = 0.f;
            cur = bb;
        }
        acc += v;
    }
    atomicAdd(&pooled[cur * OUTD + layer * DIM + col], acc);
}

// ---------------------------------------------------------------------------
extern "C" void kernel_launch(void* const* d_in, const int* in_sizes, int n_in,
                              void* d_out, int out_size) {
    const float* x     = (const float*)d_in[0];
    const void*  ei    = d_in[1];
    const void*  batch = d_in[2];

    float* out    = (float*)d_out;
    float* pooled = out;                          // [NG, OUTD]
    float* outn   = out + (long long)NG * OUTD;   // [NN, OUTD]

    float *bufB, *bufC, *stats;
    __half *whi;
    cudaGetSymbolAddress((void**)&bufB, g_bufB4);
    cudaGetSymbolAddress((void**)&bufC, g_bufC4);
    cudaGetSymbolAddress((void**)&stats, g_stats);
    cudaGetSymbolAddress((void**)&whi, g_whi);

    cudaFuncSetAttribute(layer_fused, cudaFuncAttributeMaxDynamicSharedMemorySize,
                         MLP_SMEM);

    // setup: prep (detect+edges+weights+zeros), scan, fill
    prep_kernel<<<3125, 256>>>(ei,
        (const float*)d_in[3],  (const float*)d_in[5],
        (const float*)d_in[9],  (const float*)d_in[11],
        (const float*)d_in[15], (const float*)d_in[17],
        whi, pooled);
    scan_kernel<<<1, 1024>>>();
    fillcsr_kernel<<<3125, 256>>>();

    const int woffs[6] = {0, 32768, 98304, 163840, 229376, 294912};

    const float* h = x;
    for (int l = 0; l < NL; l++) {
        int F = (l == 0) ? FIN : DIM;
        const float* b1 = (const float*)d_in[3 + 6 * l + 1];
        const float* b2 = (const float*)d_in[3 + 6 * l + 3];
        const float* gg = (const float*)d_in[3 + 6 * l + 4];
        const float* bb = (const float*)d_in[3 + 6 * l + 5];

        // ping-pong output buffer: never write the buffer being gathered from
        float* mcur = (l & 1) ? bufC : bufB;

        // fully fused layer: gather + MLP + BN stats (agg/t never in gmem)
        layer_fused<<<(NN + 127) / 128, 512, MLP_SMEM>>>(
            h, F, l > 0,
            whi + woffs[2*l], b1,
            whi + woffs[2*l+1], b2,
            mcur, stats + l * 2 * DIM, NN);

        // outputs: outn slice + pooled; publish affine for next layer
        outpool_kernel<<<(NN + ROWS_PB - 1) / ROWS_PB, DIM>>>(
            mcur, gg, bb, batch, outn, pooled, stats + l * 2 * DIM, l);

        h = mcur;
    }
}

// round 17
// speedup vs baseline: 1.0522x; 1.0522x over previous
#include <cuda_runtime.h>
#include <cuda_fp16.h>
#include <stdint.h>

#define NN   50000
#define NE   800000
#define FIN  128
#define DIM  256
#define NG   512
#define NL   3
#define OUTD (NL*DIM)   // 768
#define BN_EPS 1e-5f

// Scratch — two f32 feature buffers (ping-pong across layers; the fused
// kernel reads prev-layer features of ARBITRARY nodes while writing its own).
__device__ float4 g_bufB4[NN*DIM/4];
__device__ float4 g_bufC4[NN*DIM/4];
__device__ float  g_stats[NL][2*DIM];     // per-layer column sum, sumsq
__device__ float  g_sc[DIM], g_sh[DIM];   // published BN affine of prev layer
__device__ int    g_idx64;
// fp16 weight images, N-major ([n][k]) per (t,chunk) 128x32 tile.
__device__ __half g_whi[360448];
// CSR scratch
__device__ int g_deg[NN];
__device__ int g_rowstart[NN + 1];
__device__ int g_pos[NE];
__device__ int g_src32[NE];
__device__ int g_dst32[NE];
__device__ int g_eidx[NE];

// ---------------------------------------------------------------------------
__device__ __forceinline__ uint32_t smem_u32(const void* p) {
    uint32_t a;
    asm("{ .reg .u64 t; cvta.to.shared.u64 t, %1; cvt.u32.u64 %0, t; }" : "=r"(a) : "l"(p));
    return a;
}
__device__ __forceinline__ uint32_t pack_hf2(float a, float b) {
    uint32_t r;
    asm("cvt.rn.f16x2.f32 %0, %1, %2;" : "=r"(r) : "f"(b), "f"(a));
    return r;
}
__device__ __forceinline__ void splithf(float x, float& h, float& l) {
    __half hb = __float2half_rn(x);
    h = __half2float(hb);
    l = x - h;
}
#define LDSM_X4(r0, r1, r2, r3, addr)                                          \
    asm volatile("ldmatrix.sync.aligned.m8n8.x4.shared.b16 {%0,%1,%2,%3}, [%4];" \
                 : "=r"(r0), "=r"(r1), "=r"(r2), "=r"(r3) : "r"(addr))
#define MMA_F16(c, a0, a1, a2, a3, b0, b1)                                     \
    asm volatile(                                                              \
        "mma.sync.aligned.m16n8k16.row.col.f32.f16.f16.f32 "                   \
        "{%0,%1,%2,%3}, {%4,%5,%6,%7}, {%8,%9}, {%0,%1,%2,%3};"                \
        : "+f"(c[0]), "+f"(c[1]), "+f"(c[2]), "+f"(c[3])                       \
        : "r"(a0), "r"(a1), "r"(a2), "r"(a3), "r"(b0), "r"(b1))
#define CP_ASYNC16(dst, src)                                                   \
    asm volatile("cp.async.ca.shared.global [%0], [%1], 16;"                   \
                 :: "r"(dst), "l"(src) : "memory")
#define CP_COMMIT() asm volatile("cp.async.commit_group;" ::: "memory")

__device__ __forceinline__ long long load_idx(const void* p, long long i, int is64) {
    return is64 ? ((const long long*)p)[i] : (long long)((const int*)p)[i];
}

// ---------------------------------------------------------------------------
// prep: dtype detect, edge decode + degree histogram, fp16 weight images,
// pooled + stats zeroing. (g_deg re-zeroed by scan.)
#define WTOT 360448
__global__ void prep_kernel(const void* __restrict__ ei,
                            const float* w0, const float* w1, const float* w2,
                            const float* w3, const float* w4, const float* w5,
                            __half* __restrict__ whi,
                            float* __restrict__ pooled) {
    int stride = gridDim.x * blockDim.x;
    int gidx = blockIdx.x * blockDim.x + threadIdx.x;
    unsigned int z = 0u;
    const unsigned int* er = (const unsigned int*)ei;
#pragma unroll
    for (int k = 0; k < 8; k++) z |= er[2 * k + 1];
    int is64 = (z == 0u) ? 1 : 0;
    if (gidx == 0) g_idx64 = is64;

    if (gidx < NG * OUTD) pooled[gidx] = 0.f;
    if (gidx < NL * 2 * DIM) ((float*)g_stats)[gidx] = 0.f;

    for (int e = gidx; e < NE; e += stride) {
        int s = (int)load_idx(ei, e, is64);
        int d = (int)load_idx(ei, (long long)NE + e, is64);
        g_src32[e] = s;
        g_dst32[e] = d;
        g_pos[e] = atomicAdd(&g_deg[d], 1);
    }
    const float* ws[6] = {w0, w1, w2, w3, w4, w5};
    const int woffs[6] = {0, 32768, 98304, 163840, 229376, 294912};
    for (int idx = gidx; idx < WTOT; idx += stride) {
        int wsel, local, K;
        if (idx < 32768) { wsel = 0; local = idx; K = FIN; }
        else { wsel = 1 + ((idx - 32768) >> 16); local = (idx - 32768) & 65535; K = DIM; }
        int k = local >> 8, n = local & 255;
        int nch = K >> 5;
        int t = n >> 7, nl = n & 127, c = k >> 5, kk = k & 31;
        int off = woffs[wsel] + (t * nch + c) * 4096 + nl * 32 + kk;
        whi[off] = __float2half_rn(ws[wsel][local]);
    }
}

// Single-block scan: degrees -> rowstart (+ sentinel), then re-zero degrees.
__global__ void scan_kernel() {
    __shared__ int sm[1024];
    int t = threadIdx.x;
    const int CH = (NN + 1023) / 1024;
    int b0 = t * CH, b1 = min(b0 + CH, NN);
    int s = 0;
    for (int i = b0; i < b1; i++) s += g_deg[i];
    sm[t] = s;
    __syncthreads();
    for (int off = 1; off < 1024; off <<= 1) {
        int v = (t >= off) ? sm[t - off] : 0;
        __syncthreads();
        sm[t] += v;
        __syncthreads();
    }
    int run = (t == 0) ? 0 : sm[t - 1];
    for (int i = b0; i < b1; i++) { g_rowstart[i] = run; run += g_deg[i]; }
    if (t == 1023) g_rowstart[NN] = sm[1023];
    for (int i = b0; i < b1; i++) g_deg[i] = 0;
}

__global__ void fillcsr_kernel() {
    int stride = gridDim.x * blockDim.x;
    for (int e = blockIdx.x * blockDim.x + threadIdx.x; e < NE; e += stride)
        g_eidx[g_rowstart[g_dst32[e]] + g_pos[e]] = g_src32[e];
}

// ---------------------------------------------------------------------------
// Fully fused layer, 64-row tile / 256 threads / 2 CTAs per SM:
// gather(+BN affine) -> GEMM1 -> GEMM2 -> m + BN stats. agg/t never in gmem.
// Occupancy 2 overlaps one CTA's latency-bound gather with the co-resident
// CTA's MMA phases.
// SMEM map:
//   B stage0 [0, 20480), B stage1 [20480, 40960)
//   A/t hi   [40960,  74752)   64 rows x 528B stride (conflict-free ldmatrix)
//   A/t lo   [74752, 108544)
#define BSTG   20480
#define A_HI   40960
#define A_LO   74752
#define TSTR   528
#define ARS    80
#define MLP_SMEM 108544

__global__ void __launch_bounds__(256, 2) layer_fused(
    const float* __restrict__ h, int K1, int use_affine,
    const __half* __restrict__ W1h, const float* __restrict__ b1,
    const __half* __restrict__ W2h, const float* __restrict__ b2,
    float* __restrict__ Cf, float* __restrict__ stats, int M) {
    extern __shared__ __align__(16) char dsm[];
    int tid = threadIdx.x, wid = tid >> 5, lane = tid & 31;
    int bm = blockIdx.x;
    int nch1 = K1 >> 5;

    uint32_t sb = smem_u32(dsm);
    int m_off = (wid & 1) * 32;        // 2 M-warp groups over 64 rows
    int n_off = (wid >> 1) * 64;       // 4 N-warp groups over 256 cols

    int aRowL = (lane & 7) + ((lane >> 3) & 1) * 8;
    int aColL = (lane >> 4) * 16;
    int bRowL = ((lane >> 4) * 8) + (lane & 7);
    int bColL = ((lane >> 3) & 1) * 16;
    int gid = lane >> 2, tig = lane & 3;

    auto issueB = [&](const __half* W, int nch, int c, uint32_t stg) {
#pragma unroll
        for (int i = 0; i < 4; i++) {
            int p = tid + i * 256;     // 0..1023 uint4 slots
            int row = p >> 2, seg = p & 3;
            int t = row >> 7, nl = row & 127;
            long long srcIdx = ((long long)(t * nch + c) * 512) + nl * 4 + seg;
            CP_ASYNC16(stg + row * ARS + seg * 16, (const uint4*)W + srcIdx);
        }
    };

    // B1 chunk 0 in flight while we gather
    issueB(W1h, nch1, 0, sb);
    CP_COMMIT();

    // ===== gather phase: each of 8 warps gathers 8 nodes into SMEM A =====
    {
        int F4 = K1 >> 2;
        bool wide = (F4 == 64);
        const float4* hv = (const float4*)h;
        for (int i = 0; i < 8; i++) {
            int row = wid * 8 + i;             // 0..63
            int node = bm * 64 + row;
            float4 a0 = make_float4(0.f, 0.f, 0.f, 0.f);
            float4 a1 = a0;
            if (node < NN) {
                int start = g_rowstart[node];
                int deg = g_rowstart[node + 1] - start;
                const float4* hp = hv + (long long)node * F4 + lane;
                a0 = hp[0];
                if (wide) a1 = hp[32];
                for (int i0 = 0; i0 < deg; i0 += 32) {
                    int mye = (i0 + lane < deg) ? g_eidx[start + i0 + lane] : 0;
                    int cnt = min(32, deg - i0);
                    for (int j = 0; j < cnt; j++) {
                        int s = __shfl_sync(0xffffffffu, mye, j);
                        const float4* sp = hv + (long long)s * F4 + lane;
                        float4 v = sp[0];
                        a0.x += v.x; a0.y += v.y; a0.z += v.z; a0.w += v.w;
                        if (wide) {
                            float4 u = sp[32];
                            a1.x += u.x; a1.y += u.y; a1.z += u.z; a1.w += u.w;
                        }
                    }
                }
                if (use_affine) {
                    int c0 = lane * 4;
                    float cnt = (float)(deg + 1);
                    a0.x = g_sc[c0+0]*a0.x + cnt*g_sh[c0+0];
                    a0.y = g_sc[c0+1]*a0.y + cnt*g_sh[c0+1];
                    a0.z = g_sc[c0+2]*a0.z + cnt*g_sh[c0+2];
                    a0.w = g_sc[c0+3]*a0.w + cnt*g_sh[c0+3];
                    if (wide) {
                        int c1 = 128 + c0;
                        a1.x = g_sc[c1+0]*a1.x + cnt*g_sh[c1+0];
                        a1.y = g_sc[c1+1]*a1.y + cnt*g_sh[c1+1];
                        a1.z = g_sc[c1+2]*a1.z + cnt*g_sh[c1+2];
                        a1.w = g_sc[c1+3]*a1.w + cnt*g_sh[c1+3];
                    }
                }
            }
            uint32_t ad = sb + A_HI + row * TSTR + lane * 8;
            {
                float h0,l0,h1,l1,h2,l2,h3,l3;
                splithf(a0.x,h0,l0); splithf(a0.y,h1,l1);
                splithf(a0.z,h2,l2); splithf(a0.w,h3,l3);
                asm volatile("st.shared.v2.b32 [%0], {%1,%2};"
                             :: "r"(ad), "r"(pack_hf2(h0,h1)), "r"(pack_hf2(h2,h3)) : "memory");
                asm volatile("st.shared.v2.b32 [%0], {%1,%2};"
                             :: "r"(ad + (A_LO - A_HI)), "r"(pack_hf2(l0,l1)), "r"(pack_hf2(l2,l3)) : "memory");
            }
            if (wide) {
                float h0,l0,h1,l1,h2,l2,h3,l3;
                splithf(a1.x,h0,l0); splithf(a1.y,h1,l1);
                splithf(a1.z,h2,l2); splithf(a1.w,h3,l3);
                asm volatile("st.shared.v2.b32 [%0], {%1,%2};"
                             :: "r"(ad + 256), "r"(pack_hf2(h0,h1)), "r"(pack_hf2(h2,h3)) : "memory");
                asm volatile("st.shared.v2.b32 [%0], {%1,%2};"
                             :: "r"(ad + 256 + (A_LO - A_HI)), "r"(pack_hf2(l0,l1)), "r"(pack_hf2(l2,l3)) : "memory");
            }
        }
    }
    __syncthreads();

    float acc[2][8][4] = {};

    // ===== phase 1: t = relu(A @ W1 + b1); A read in place from SMEM =====
    for (int c = 0; c < nch1; c++) {
        uint32_t stg = sb + (c & 1) * BSTG;
        if (c + 1 < nch1) {
            issueB(W1h, nch1, c + 1, sb + ((c + 1) & 1) * BSTG);
            CP_COMMIT();
            asm volatile("cp.async.wait_group 1;" ::: "memory");
        } else {
            asm volatile("cp.async.wait_group 0;" ::: "memory");
        }
        __syncthreads();
#pragma unroll
        for (int ks = 0; ks < 2; ks++) {
            uint32_t aH[2][4], aL[2][4];
#pragma unroll
            for (int mt = 0; mt < 2; mt++) {
                uint32_t ad = sb + A_HI + (m_off + mt * 16 + aRowL) * TSTR + c * 64 + ks * 32 + aColL;
                LDSM_X4(aH[mt][0], aH[mt][1], aH[mt][2], aH[mt][3], ad);
                LDSM_X4(aL[mt][0], aL[mt][1], aL[mt][2], aL[mt][3], ad + (A_LO - A_HI));
            }
#pragma unroll
            for (int p = 0; p < 4; p++) {
                uint32_t bH[2][2];
                uint32_t ad = stg + (n_off + p * 16 + bRowL) * ARS + ks * 32 + bColL;
                LDSM_X4(bH[0][0], bH[0][1], bH[1][0], bH[1][1], ad);
#pragma unroll
                for (int mt = 0; mt < 2; mt++)
#pragma unroll
                    for (int q = 0; q < 2; q++)
                        MMA_F16(acc[mt][2*p+q], aH[mt][0], aH[mt][1], aH[mt][2], aH[mt][3],
                                bH[q][0], bH[q][1]);
#pragma unroll
                for (int mt = 0; mt < 2; mt++)
#pragma unroll
                    for (int q = 0; q < 2; q++)
                        MMA_F16(acc[mt][2*p+q], aL[mt][0], aL[mt][1], aL[mt][2], aL[mt][3],
                                bH[q][0], bH[q][1]);
            }
        }
        __syncthreads();
    }

    // ===== phase-1 epilogue: bias+relu+split -> t OVERWRITES A region =====
#pragma unroll
    for (int nt = 0; nt < 8; nt++) {
        int col = n_off + nt * 8 + tig * 2;
        float c0 = b1[col], c1 = b1[col + 1];
#pragma unroll
        for (int mt = 0; mt < 2; mt++) {
            float* cc = acc[mt][nt];
            int r0 = m_off + mt * 16 + gid;
            {
                float o0 = fmaxf(cc[0] + c0, 0.f);
                float o1 = fmaxf(cc[1] + c1, 0.f);
                float h0,l0,h1,l1;
                splithf(o0,h0,l0); splithf(o1,h1,l1);
                uint32_t ad = sb + A_HI + r0 * TSTR + col * 2;
                asm volatile("st.shared.b32 [%0], %1;" :: "r"(ad), "r"(pack_hf2(h0,h1)) : "memory");
                asm volatile("st.shared.b32 [%0], %1;" :: "r"(ad + (A_LO - A_HI)), "r"(pack_hf2(l0,l1)) : "memory");
            }
            {
                float o2 = fmaxf(cc[2] + c0, 0.f);
                float o3 = fmaxf(cc[3] + c1, 0.f);
                float h2,l2,h3,l3;
                splithf(o2,h2,l2); splithf(o3,h3,l3);
                uint32_t ad = sb + A_HI + (r0 + 8) * TSTR + col * 2;
                asm volatile("st.shared.b32 [%0], %1;" :: "r"(ad), "r"(pack_hf2(h2,h3)) : "memory");
                asm volatile("st.shared.b32 [%0], %1;" :: "r"(ad + (A_LO - A_HI)), "r"(pack_hf2(l2,l3)) : "memory");
            }
            cc[0] = cc[1] = cc[2] = cc[3] = 0.f;
        }
    }
    __syncthreads();

    // ===== phase 2: m = relu(t @ W2 + b2) =====
    issueB(W2h, 8, 0, sb);
    CP_COMMIT();
    for (int c = 0; c < 8; c++) {
        uint32_t stg = sb + (c & 1) * BSTG;
        if (c + 1 < 8) {
            issueB(W2h, 8, c + 1, sb + ((c + 1) & 1) * BSTG);
            CP_COMMIT();
            asm volatile("cp.async.wait_group 1;" ::: "memory");
        } else {
            asm volatile("cp.async.wait_group 0;" ::: "memory");
        }
        __syncthreads();
#pragma unroll
        for (int ks = 0; ks < 2; ks++) {
            uint32_t aH[2][4], aL[2][4];
#pragma unroll
            for (int mt = 0; mt < 2; mt++) {
                uint32_t ad = sb + A_HI + (m_off + mt * 16 + aRowL) * TSTR + c * 64 + ks * 32 + aColL;
                LDSM_X4(aH[mt][0], aH[mt][1], aH[mt][2], aH[mt][3], ad);
                LDSM_X4(aL[mt][0], aL[mt][1], aL[mt][2], aL[mt][3], ad + (A_LO - A_HI));
            }
#pragma unroll
            for (int p = 0; p < 4; p++) {
                uint32_t bH[2][2];
                uint32_t ad = stg + (n_off + p * 16 + bRowL) * ARS + ks * 32 + bColL;
                LDSM_X4(bH[0][0], bH[0][1], bH[1][0], bH[1][1], ad);
#pragma unroll
                for (int mt = 0; mt < 2; mt++)
#pragma unroll
                    for (int q = 0; q < 2; q++)
                        MMA_F16(acc[mt][2*p+q], aH[mt][0], aH[mt][1], aH[mt][2], aH[mt][3],
                                bH[q][0], bH[q][1]);
#pragma unroll
                for (int mt = 0; mt < 2; mt++)
#pragma unroll
                    for (int q = 0; q < 2; q++)
                        MMA_F16(acc[mt][2*p+q], aL[mt][0], aL[mt][1], aL[mt][2], aL[mt][3],
                                bH[q][0], bH[q][1]);
            }
        }
        __syncthreads();
    }

    // ===== final epilogue: bias + relu, f32 out + fused BN stats =====
#pragma unroll
    for (int nt = 0; nt < 8; nt++) {
        int col = n_off + nt * 8 + tig * 2;
        float c0 = b2[col], c1 = b2[col + 1];
        float s0 = 0.f, s1 = 0.f, q0 = 0.f, q1 = 0.f;
#pragma unroll
        for (int mt = 0; mt < 2; mt++) {
            int r0 = bm * 64 + m_off + mt * 16 + gid;
            float* cc = acc[mt][nt];
            if (r0 < M) {
                float o0 = fmaxf(cc[0] + c0, 0.f);
                float o1 = fmaxf(cc[1] + c1, 0.f);
                float2 o; o.x = o0; o.y = o1;
                *(float2*)(Cf + (long long)r0 * 256 + col) = o;
                s0 += o0; s1 += o1; q0 += o0 * o0; q1 += o1 * o1;
            }
            if (r0 + 8 < M) {
                float o2 = fmaxf(cc[2] + c0, 0.f);
                float o3 = fmaxf(cc[3] + c1, 0.f);
                float2 o; o.x = o2; o.y = o3;
                *(float2*)(Cf + (long long)(r0 + 8) * 256 + col) = o;
                s0 += o2; s1 += o3; q0 += o2 * o2; q1 += o3 * o3;
            }
        }
#pragma unroll
        for (int m = 4; m < 32; m <<= 1) {
            s0 += __shfl_xor_sync(0xffffffffu, s0, m);
            s1 += __shfl_xor_sync(0xffffffffu, s1, m);
            q0 += __shfl_xor_sync(0xffffffffu, q0, m);
            q1 += __shfl_xor_sync(0xffffffffu, q1, m);
        }
        if (gid == 0) {
            atomicAdd(&stats[col], s0);
            atomicAdd(&stats[col + 1], s1);
            atomicAdd(&stats[DIM + col], q0);
            atomicAdd(&stats[DIM + col + 1], q1);
        }
    }
}

// ---------------------------------------------------------------------------
// Per-layer output: norm(m) -> outn slice + pooled sums. Block 0 publishes
// the affine for the next layer's fused gather.
#define ROWS_PB 128
__global__ void outpool_kernel(const float* __restrict__ m,
                               const float* __restrict__ g, const float* __restrict__ b,
                               const void* __restrict__ batch,
                               float* __restrict__ outn,
                               float* __restrict__ pooled,
                               const float* __restrict__ stats, int layer) {
    int col = threadIdx.x;
    int is64 = g_idx64;
    float mu  = stats[col] * (1.f / NN);
    float var = stats[DIM + col] * (1.f / NN) - mu * mu;
    float sc  = g[col] * rsqrtf(var + BN_EPS);
    float sh  = b[col] - mu * sc;
    if (blockIdx.x == 0) { g_sc[col] = sc; g_sh[col] = sh; }

    int n0 = blockIdx.x * ROWS_PB;
    int n1 = min(n0 + ROWS_PB, NN);
    float acc = 0.f;
    long long cur = load_idx(batch, n0, is64);
    for (int n = n0; n < n1; n++) {
        float v = m[(long long)n * DIM + col] * sc + sh;
        outn[(long long)n * OUTD + layer * DIM + col] = v;
        long long bb = load_idx(batch, n, is64);
        if (bb != cur) {
            atomicAdd(&pooled[cur * OUTD + layer * DIM + col], acc);
            acc = 0.f;
            cur = bb;
        }
        acc += v;
    }
    atomicAdd(&pooled[cur * OUTD + layer * DIM + col], acc);
}

// ---------------------------------------------------------------------------
extern "C" void kernel_launch(void* const* d_in, const int* in_sizes, int n_in,
                              void* d_out, int out_size) {
    const float* x     = (const float*)d_in[0];
    const void*  ei    = d_in[1];
    const void*  batch = d_in[2];

    float* out    = (float*)d_out;
    float* pooled = out;                          // [NG, OUTD]
    float* outn   = out + (long long)NG * OUTD;   // [NN, OUTD]

    float *bufB, *bufC, *stats;
    __half *whi;
    cudaGetSymbolAddress((void**)&bufB, g_bufB4);
    cudaGetSymbolAddress((void**)&bufC, g_bufC4);
    cudaGetSymbolAddress((void**)&stats, g_stats);
    cudaGetSymbolAddress((void**)&whi, g_whi);

    cudaFuncSetAttribute(layer_fused, cudaFuncAttributeMaxDynamicSharedMemorySize,
                         MLP_SMEM);

    // setup: prep (detect+edges+weights+zeros), scan, fill
    prep_kernel<<<3125, 256>>>(ei,
        (const float*)d_in[3],  (const float*)d_in[5],
        (const float*)d_in[9],  (const float*)d_in[11],
        (const float*)d_in[15], (const float*)d_in[17],
        whi, pooled);
    scan_kernel<<<1, 1024>>>();
    fillcsr_kernel<<<3125, 256>>>();

    const int woffs[6] = {0, 32768, 98304, 163840, 229376, 294912};

    const float* h = x;
    for (int l = 0; l < NL; l++) {
        int F = (l == 0) ? FIN : DIM;
        const float* b1 = (const float*)d_in[3 + 6 * l + 1];
        const float* b2 = (const float*)d_in[3 + 6 * l + 3];
        const float* gg = (const float*)d_in[3 + 6 * l + 4];
        const float* bb = (const float*)d_in[3 + 6 * l + 5];

        // ping-pong output buffer: never write the buffer being gathered from
        float* mcur = (l & 1) ? bufC : bufB;

        // fully fused layer: gather + MLP + BN stats, 2 CTAs/SM for overlap
        layer_fused<<<(NN + 63) / 64, 256, MLP_SMEM>>>(
            h, F, l > 0,
            whi + woffs[2*l], b1,
            whi + woffs[2*l+1], b2,
            mcur, stats + l * 2 * DIM, NN);

        // outputs: outn slice + pooled; publish affine for next layer
        outpool_kernel<<<(NN + ROWS_PB - 1) / ROWS_PB, DIM>>>(
            mcur, gg, bb, batch, outn, pooled, stats + l * 2 * DIM, l);

        h = mcur;
    }
}